// round 1
// baseline (speedup 1.0000x reference)
#include <cuda_runtime.h>
#include <cuda_bf16.h>
#include <cstdint>

// Problem constants (fixed shapes for this problem instance)
#define N_TOK  2048
#define D_IN   2048
#define D_OUT  2048
#define N_EXP  8
#define TOPK   2
#define NK     (N_TOK * TOPK)   // 4096 (token, slot) rows total

// Tiling
#define BM 64
#define BN 64
#define BK 16
#define MT (NK / BM)            // 64 m-tiles max per expert (worst case all rows in one expert)
#define PAD 4                   // smem row padding (stride 20 words -> conflict-free frag loads)

__device__ __forceinline__ uint32_t f32_to_tf32(float x) {
    uint32_t r;
    asm("cvt.rna.tf32.f32 %0, %1;" : "=r"(r) : "f"(x));
    return r;
}

__global__ __launch_bounds__(256, 2) void moe_gemm_tf32(
    const float* __restrict__ X,      // [N_TOK, D_IN]
    const float* __restrict__ W,      // [E, D_OUT, D_IN]
    const int*   __restrict__ scat,   // sorted_scattered_idxs [NK]
    const int*   __restrict__ offs,   // expert_offsets [E] (inclusive cumsum)
    const float* __restrict__ gates,  // [N_TOK, TOPK] flat
    float*       __restrict__ out)    // [N_TOK, D_OUT], pre-zeroed
{
    const int e   = blockIdx.y / MT;
    const int mt  = blockIdx.y % MT;
    const int start = (e == 0) ? 0 : offs[e - 1];
    const int end   = offs[e];
    const int row0  = start + mt * BM;
    if (row0 >= end) return;   // early-exit for padded m-tiles

    __shared__ uint32_t As[BM][BK + PAD];
    __shared__ uint32_t Bs[BN][BK + PAD];
    __shared__ int      s_tok[BM];
    __shared__ float    s_gate[BM];

    const int tid = threadIdx.x;

    // Per-row routing metadata for this m-tile
    if (tid < BM) {
        int p = row0 + tid;
        int tok = 0; float g = 0.0f;
        if (p < end) {
            int j = scat[p];          // flat (token, slot) index
            tok = j / TOPK;
            g   = gates[j];           // gates flat index == j
        }
        s_tok[tid]  = tok;
        s_gate[tid] = g;
    }
    __syncthreads();

    const int lane = tid & 31, warp = tid >> 5;
    const int wm = warp >> 2;          // 0..1  (32 rows each)
    const int wn = warp & 3;           // 0..3  (16 cols each)
    const int g4 = lane >> 2;          // groupID 0..7
    const int tg = lane & 3;           // threadID_in_group 0..3

    // Global-load mapping: 256 threads load 64 rows x 16 cols (one float4 each)
    const int lr = tid >> 2;           // 0..63 row
    const int lc = (tid & 3) * 4;      // 0,4,8,12 col

    const float* Wbase = W + (size_t)e * D_OUT * D_IN + (size_t)(blockIdx.x * BN) * D_IN;
    const float* a_ptr = X + (size_t)s_tok[lr] * D_IN + lc;
    const float* b_ptr = Wbase + (size_t)lr * D_IN + lc;

    float c[2][2][4];
    #pragma unroll
    for (int i = 0; i < 2; i++)
        #pragma unroll
        for (int j = 0; j < 2; j++)
            #pragma unroll
            for (int q = 0; q < 4; q++) c[i][j][q] = 0.0f;

    for (int k0 = 0; k0 < D_IN; k0 += BK) {
        float4 av = *(const float4*)(a_ptr + k0);
        float4 bv = *(const float4*)(b_ptr + k0);

        __syncthreads();   // previous iteration's compute done before smem overwrite
        As[lr][lc + 0] = f32_to_tf32(av.x);
        As[lr][lc + 1] = f32_to_tf32(av.y);
        As[lr][lc + 2] = f32_to_tf32(av.z);
        As[lr][lc + 3] = f32_to_tf32(av.w);
        Bs[lr][lc + 0] = f32_to_tf32(bv.x);
        Bs[lr][lc + 1] = f32_to_tf32(bv.y);
        Bs[lr][lc + 2] = f32_to_tf32(bv.z);
        Bs[lr][lc + 3] = f32_to_tf32(bv.w);
        __syncthreads();

        #pragma unroll
        for (int kk = 0; kk < BK; kk += 8) {
            #pragma unroll
            for (int mi = 0; mi < 2; mi++) {
                const int mb = wm * 32 + mi * 16;
                uint32_t a0 = As[mb + g4    ][kk + tg    ];
                uint32_t a1 = As[mb + g4 + 8][kk + tg    ];
                uint32_t a2 = As[mb + g4    ][kk + tg + 4];
                uint32_t a3 = As[mb + g4 + 8][kk + tg + 4];
                #pragma unroll
                for (int nj = 0; nj < 2; nj++) {
                    const int nb = wn * 16 + nj * 8;
                    uint32_t b0 = Bs[nb + g4][kk + tg    ];
                    uint32_t b1 = Bs[nb + g4][kk + tg + 4];
                    float* cc = c[mi][nj];
                    asm volatile(
                        "mma.sync.aligned.m16n8k8.row.col.f32.tf32.tf32.f32 "
                        "{%0,%1,%2,%3}, {%4,%5,%6,%7}, {%8,%9}, {%0,%1,%2,%3};\n"
                        : "+f"(cc[0]), "+f"(cc[1]), "+f"(cc[2]), "+f"(cc[3])
                        : "r"(a0), "r"(a1), "r"(a2), "r"(a3), "r"(b0), "r"(b1));
                }
            }
        }
    }

    // Epilogue: out[tok, col] += gate * acc   (atomic; TOPK=2 contributions/element)
    const int cn0 = blockIdx.x * BN;
    #pragma unroll
    for (int mi = 0; mi < 2; mi++) {
        const int rbase = wm * 32 + mi * 16 + g4;
        #pragma unroll
        for (int half = 0; half < 2; half++) {
            const int r = rbase + half * 8;
            const int p = row0 + r;
            if (p < end) {
                const float g = s_gate[r];
                float* orow = out + (size_t)s_tok[r] * D_OUT;
                #pragma unroll
                for (int nj = 0; nj < 2; nj++) {
                    const int col = cn0 + wn * 16 + nj * 8 + 2 * tg;
                    atomicAdd(&orow[col    ], g * c[mi][nj][half * 2 + 0]);
                    atomicAdd(&orow[col + 1], g * c[mi][nj][half * 2 + 1]);
                }
            }
        }
    }
}

extern "C" void kernel_launch(void* const* d_in, const int* in_sizes, int n_in,
                              void* d_out, int out_size)
{
    // Input order per metadata: inputs, weight, k, sorted_expert_idxs,
    // sorted_scattered_idxs, padded_block_idxs, expert_offsets, gates.
    // Be robust to the scalar "k" being dropped by the harness (n_in == 7).
    const float* X;
    const float* W;
    const int*   scat;
    const int*   offs;
    const float* gates;

    X = (const float*)d_in[0];
    W = (const float*)d_in[1];
    if (n_in >= 8) {
        scat  = (const int*)  d_in[4];
        offs  = (const int*)  d_in[6];
        gates = (const float*)d_in[7];
    } else {
        scat  = (const int*)  d_in[3];
        offs  = (const int*)  d_in[5];
        gates = (const float*)d_in[6];
    }

    float* out = (float*)d_out;
    cudaMemsetAsync(out, 0, (size_t)N_TOK * D_OUT * sizeof(float));

    dim3 grid(D_OUT / BN, N_EXP * MT);   // 32 x 512
    moe_gemm_tf32<<<grid, 256>>>(X, W, scat, offs, gates, out);
}

// round 3
// speedup vs baseline: 1.3454x; 1.3454x over previous
#include <cuda_runtime.h>
#include <cuda_bf16.h>
#include <cstdint>

// ---------------- problem constants ----------------
#define N_TOK  2048
#define D_IN   2048
#define D_OUT  2048
#define N_EXP  8
#define TOPK   2
#define NK     (N_TOK * TOPK)        // 4096 rows

// ---------------- tiling ----------------
#define BM 128
#define BN 128
#define BK 32
#define STAGES 3
#define KITERS (D_IN / BK)           // 64
#define MT (NK / BM)                 // 32 m-tiles per expert worst case
#define PADW 36                      // smem words per row (32 + 4 pad) -> conflict-free frags
#define STAGE_WORDS ((BM + BN) * PADW)   // 9216 words = 36864 B per stage

// ---------------- scratch ----------------
__device__ uint32_t g_x32[(size_t)N_TOK * D_IN];   // rna-rounded tf32 copy of X (16 MB)

__device__ __forceinline__ uint32_t f32_to_tf32(float x) {
    uint32_t r; asm("cvt.rna.tf32.f32 %0, %1;" : "=r"(r) : "f"(x)); return r;
}

// ---------------- pre-convert X -> tf32(rna) ----------------
__global__ void cvtX(const float* __restrict__ X) {
    size_t i = (size_t)(blockIdx.x * blockDim.x + threadIdx.x) * 4;
    float4 v = *(const float4*)(X + i);
    uint4 o;
    o.x = f32_to_tf32(v.x); o.y = f32_to_tf32(v.y);
    o.z = f32_to_tf32(v.z); o.w = f32_to_tf32(v.w);
    *(uint4*)(g_x32 + i) = o;
}

// ---------------- main grouped GEMM ----------------
__global__ __launch_bounds__(256, 2) void moe_mma(
    const float* __restrict__ W,
    const int*   __restrict__ scat,
    const int*   __restrict__ offs,
    const float* __restrict__ gates,
    float*       __restrict__ out)
{
    const int e     = blockIdx.y / MT;
    const int mt    = blockIdx.y % MT;
    const int start = (e == 0) ? 0 : offs[e - 1];
    const int end   = offs[e];
    const int row0  = start + mt * BM;
    if (row0 >= end) return;
    const int n0 = blockIdx.x * BN;

    extern __shared__ uint32_t sm[];
    __shared__ int   s_tok[BM];
    __shared__ float s_gate[BM];

    const int tid  = threadIdx.x;
    const int warp = tid >> 5;
    const int lane = tid & 31;

    if (tid < BM) {
        int p = row0 + tid; int tok = 0; float g = 0.0f;
        if (p < end) { int j = scat[p]; tok = j / TOPK; g = gates[j]; }
        s_tok[tid] = tok; s_gate[tid] = g;
    }
    __syncthreads();

    // ---- load mapping: 2 threads per row, 4 x 16B chunks each ----
    const int lrow = tid >> 1;
    const int lcol = (tid & 1) * 16;

    const uint32_t* ga = g_x32 + (size_t)s_tok[lrow] * D_IN + lcol;
    const float*    gb = W + (size_t)e * D_OUT * D_IN + (size_t)(n0 + lrow) * D_IN + lcol;

    uint32_t sa_base, sb_base;
    {
        uint32_t base = (uint32_t)__cvta_generic_to_shared(sm);
        sa_base = base + (uint32_t)(lrow * PADW + lcol) * 4u;
        sb_base = sa_base + (uint32_t)(BM * PADW) * 4u;
    }

    #define LOAD_STAGE(st, it)                                                     \
        do {                                                                       \
            uint32_t _sa = sa_base + (uint32_t)(st) * (STAGE_WORDS * 4);           \
            uint32_t _sb = sb_base + (uint32_t)(st) * (STAGE_WORDS * 4);           \
            const uint32_t* _ga = ga + (it) * BK;                                  \
            const float*    _gb = gb + (it) * BK;                                  \
            _Pragma("unroll")                                                      \
            for (int c = 0; c < 4; c++) {                                          \
                asm volatile("cp.async.cg.shared.global [%0], [%1], 16;"           \
                             :: "r"(_sa + c * 16), "l"(_ga + c * 4) : "memory");   \
                asm volatile("cp.async.cg.shared.global [%0], [%1], 16;"           \
                             :: "r"(_sb + c * 16), "l"(_gb + c * 4) : "memory");   \
            }                                                                      \
        } while (0)

    // prologue: stages 0,1
    LOAD_STAGE(0, 0);
    asm volatile("cp.async.commit_group;" ::: "memory");
    LOAD_STAGE(1, 1);
    asm volatile("cp.async.commit_group;" ::: "memory");

    // ---- fragment geometry: warps 2(m) x 4(n); warp tile 64x32 ----
    const int wm = warp >> 2;            // 0..1
    const int wn = warp & 3;             // 0..3
    const int g4 = lane >> 2;            // 0..7
    const int tg = lane & 3;             // 0..3

    float acc[4][4][4];
    #pragma unroll
    for (int i = 0; i < 4; i++)
        #pragma unroll
        for (int j = 0; j < 4; j++)
            #pragma unroll
            for (int q = 0; q < 4; q++) acc[i][j][q] = 0.0f;

    for (int it = 0; it < KITERS; it++) {
        asm volatile("cp.async.wait_group 1;" ::: "memory");
        __syncthreads();

        const int st = it % STAGES;
        const uint32_t* As = sm + st * STAGE_WORDS;
        const uint32_t* Bs = As + BM * PADW;

        #pragma unroll
        for (int kk = 0; kk < 4; kk++) {
            const int kc = kk * 8 + tg;
            uint32_t a[4][4], b[4][2];
            #pragma unroll
            for (int mi = 0; mi < 4; mi++) {
                const int r = wm * 64 + mi * 16 + g4;
                a[mi][0] = As[r * PADW + kc];
                a[mi][1] = As[(r + 8) * PADW + kc];
                a[mi][2] = As[r * PADW + kc + 4];
                a[mi][3] = As[(r + 8) * PADW + kc + 4];
            }
            #pragma unroll
            for (int nj = 0; nj < 4; nj++) {
                const int n = wn * 32 + nj * 8 + g4;
                b[nj][0] = Bs[n * PADW + kc];
                b[nj][1] = Bs[n * PADW + kc + 4];
            }
            #pragma unroll
            for (int mi = 0; mi < 4; mi++)
                #pragma unroll
                for (int nj = 0; nj < 4; nj++) {
                    float* cc = acc[mi][nj];
                    asm volatile(
                        "mma.sync.aligned.m16n8k8.row.col.f32.tf32.tf32.f32 "
                        "{%0,%1,%2,%3}, {%4,%5,%6,%7}, {%8,%9}, {%0,%1,%2,%3};\n"
                        : "+f"(cc[0]), "+f"(cc[1]), "+f"(cc[2]), "+f"(cc[3])
                        : "r"(a[mi][0]), "r"(a[mi][1]), "r"(a[mi][2]), "r"(a[mi][3]),
                          "r"(b[nj][0]), "r"(b[nj][1]));
                }
        }

        if (it + 2 < KITERS) LOAD_STAGE((it + 2) % STAGES, it + 2);
        asm volatile("cp.async.commit_group;" ::: "memory");
    }

    // ---- epilogue: gate-scaled atomic accumulate into out ----
    #pragma unroll
    for (int mi = 0; mi < 4; mi++) {
        #pragma unroll
        for (int half = 0; half < 2; half++) {
            const int r = wm * 64 + mi * 16 + g4 + half * 8;
            const int p = row0 + r;
            if (p < end) {
                const float g = s_gate[r];
                float* orow = out + (size_t)s_tok[r] * D_OUT + n0;
                #pragma unroll
                for (int nj = 0; nj < 4; nj++) {
                    const int col = wn * 32 + nj * 8 + 2 * tg;
                    atomicAdd(&orow[col    ], g * acc[mi][nj][half * 2 + 0]);
                    atomicAdd(&orow[col + 1], g * acc[mi][nj][half * 2 + 1]);
                }
            }
        }
    }
}

// ---------------- launch ----------------
extern "C" void kernel_launch(void* const* d_in, const int* in_sizes, int n_in,
                              void* d_out, int out_size)
{
    const float* X = (const float*)d_in[0];
    const float* W = (const float*)d_in[1];
    const int *scat, *offs; const float* gates;
    if (n_in >= 8) {
        scat = (const int*)d_in[4]; offs = (const int*)d_in[6]; gates = (const float*)d_in[7];
    } else {
        scat = (const int*)d_in[3]; offs = (const int*)d_in[5]; gates = (const float*)d_in[6];
    }
    float* out = (float*)d_out;

    cvtX<<<(N_TOK * D_IN) / (256 * 4), 256>>>(X);
    cudaMemsetAsync(out, 0, (size_t)N_TOK * D_OUT * sizeof(float));

    const int dyn_smem = STAGES * STAGE_WORDS * 4;   // 110592 B
    static bool attr_set = false;
    if (!attr_set) {
        cudaFuncSetAttribute(moe_mma, cudaFuncAttributeMaxDynamicSharedMemorySize, dyn_smem);
        attr_set = true;
    }

    dim3 grid(D_OUT / BN, N_EXP * MT);   // 16 x 256
    moe_mma<<<grid, 256, dyn_smem>>>(W, scat, offs, gates, out);
}

// round 4
// speedup vs baseline: 1.8129x; 1.3475x over previous
#include <cuda_runtime.h>
#include <cuda_bf16.h>
#include <cstdint>

// ---------------- problem constants ----------------
#define N_TOK  2048
#define D_IN   2048
#define D_OUT  2048
#define N_EXP  8
#define TOPK   2
#define NK     (N_TOK * TOPK)        // 4096 rows

// ---------------- tiling ----------------
#define BM 128
#define BN 128
#define BK 32                        // k floats per stage (128 B per row)
#define STAGES 3
#define KITERS (D_IN / BK)           // 64
#define MT (NK / BM)                 // 32 m-tiles per expert worst case
#define ROWB 128u                    // bytes per smem row (no pad, swizzled)
#define STAGE_BYTES ((BM + BN) * 128)      // 32768 B per stage

// ---------------- scratch: gathered + tf32(rna) rows, padded tail ----------------
__device__ uint32_t g_xg[(size_t)(NK + BM) * D_IN];   // ~34.6 MB

__device__ __forceinline__ uint32_t f32_to_tf32(float x) {
    uint32_t r; asm("cvt.rna.tf32.f32 %0, %1;" : "=r"(r) : "f"(x)); return r;
}

// ---------------- prep: gather rows into sorted order + rna convert ----------------
__global__ void prep(const float* __restrict__ X, const int* __restrict__ scat) {
    const int p = blockIdx.x;                 // 0..NK-1 sorted position
    const int tok = scat[p] / TOPK;
    const float4* src = (const float4*)(X + (size_t)tok * D_IN);
    uint4* dst = (uint4*)(g_xg + (size_t)p * D_IN);
    const int t = threadIdx.x;                // 256 threads, 512 float4/row
    #pragma unroll
    for (int q = 0; q < 2; q++) {
        float4 v = src[t + q * 256];
        uint4 o;
        o.x = f32_to_tf32(v.x); o.y = f32_to_tf32(v.y);
        o.z = f32_to_tf32(v.z); o.w = f32_to_tf32(v.w);
        dst[t + q * 256] = o;
    }
}

// swizzled smem byte offset for (row, 16B-chunk)
__device__ __forceinline__ uint32_t swz_off(uint32_t r, uint32_t chunk) {
    return r * ROWB + (((chunk ^ (r & 7u))) << 4);
}

// ---------------- main grouped GEMM ----------------
__global__ __launch_bounds__(256, 2) void moe_mma(
    const float* __restrict__ W,
    const int*   __restrict__ scat,
    const int*   __restrict__ offs,
    const float* __restrict__ gates,
    float*       __restrict__ out)
{
    const int e     = blockIdx.y / MT;
    const int mt    = blockIdx.y % MT;
    const int start = (e == 0) ? 0 : offs[e - 1];
    const int end   = offs[e];
    const int row0  = start + mt * BM;
    if (row0 >= end) return;
    const int n0 = blockIdx.x * BN;

    extern __shared__ uint32_t sm[];
    __shared__ int   s_tok[BM];
    __shared__ float s_gate[BM];

    const int tid  = threadIdx.x;
    const int warp = tid >> 5;
    const int lane = tid & 31;

    if (tid < BM) {
        int p = row0 + tid; int tok = 0; float g = 0.0f;
        if (p < end) { int j = scat[p]; tok = j / TOPK; g = gates[j]; }
        s_tok[tid] = tok; s_gate[tid] = g;
    }

    // ---- global->smem mapping: 2 threads per row, 4 x 16B chunks each ----
    const int lrow = tid >> 1;               // 0..127
    const int h    = tid & 1;                // chunk half: chunks 4h..4h+3
    const uint32_t* ga = g_xg + (size_t)(row0 + lrow) * D_IN + h * 16;
    const float*    gb = W + (size_t)e * D_OUT * D_IN + (size_t)(n0 + lrow) * D_IN + h * 16;

    const uint32_t smb = (uint32_t)__cvta_generic_to_shared(sm);
    // per-thread swizzled dest offsets for the 4 chunks
    uint32_t dstoff[4];
    #pragma unroll
    for (int q = 0; q < 4; q++) dstoff[q] = swz_off((uint32_t)lrow, (uint32_t)(4 * h + q));

    #define LOAD_STAGE(st, it)                                                       \
        do {                                                                         \
            uint32_t _sa = smb + (uint32_t)(st) * STAGE_BYTES;                       \
            uint32_t _sb = _sa + BM * ROWB;                                          \
            const uint32_t* _ga = ga + (size_t)(it) * BK;                            \
            const float*    _gb = gb + (size_t)(it) * BK;                            \
            _Pragma("unroll")                                                        \
            for (int q = 0; q < 4; q++) {                                            \
                asm volatile("cp.async.cg.shared.global [%0], [%1], 16;"             \
                             :: "r"(_sa + dstoff[q]), "l"(_ga + q * 4) : "memory");  \
                asm volatile("cp.async.cg.shared.global [%0], [%1], 16;"             \
                             :: "r"(_sb + dstoff[q]), "l"(_gb + q * 4) : "memory");  \
            }                                                                        \
        } while (0)

    LOAD_STAGE(0, 0);
    asm volatile("cp.async.commit_group;" ::: "memory");
    LOAD_STAGE(1, 1);
    asm volatile("cp.async.commit_group;" ::: "memory");

    // ---- fragment geometry: warps 2(m) x 4(n); warp tile 64x32 ----
    const int wm = warp >> 2;                // 0..1
    const int wn = warp & 3;                 // 0..3
    const int g4 = lane >> 2;
    const int tg = lane & 3;
    const int x7 = lane & 7;

    // ldmatrix per-lane bases
    const uint32_t ar = (uint32_t)(wm * 64 + (lane & 15));     // + mi*16
    const uint32_t as = (uint32_t)(lane >> 4);                 // 0/1 (k-chunk select)
    const uint32_t br = (uint32_t)(wn * 32 + x7);              // + nj*8
    const uint32_t bs = (uint32_t)((lane >> 3) & 1);
    uint32_t aoff[4], boff[4];
    #pragma unroll
    for (int kk = 0; kk < 4; kk++) {
        aoff[kk] = (uint32_t)(((2 * kk + (int)as) ^ x7) << 4);
        boff[kk] = (uint32_t)(((2 * kk + (int)bs) ^ x7) << 4);
    }

    float acc[4][4][4];
    #pragma unroll
    for (int i = 0; i < 4; i++)
        #pragma unroll
        for (int j = 0; j < 4; j++)
            #pragma unroll
            for (int q = 0; q < 4; q++) acc[i][j][q] = 0.0f;

    __syncthreads();   // s_tok/s_gate ready (also covered by pipeline barriers later)

    #pragma unroll 1
    for (int it = 0; it < KITERS; it++) {
        asm volatile("cp.async.wait_group 1;" ::: "memory");
        __syncthreads();

        if (it + 2 < KITERS) {
            LOAD_STAGE((it + 2) % STAGES, it + 2);
            asm volatile("cp.async.commit_group;" ::: "memory");
        }

        const int st = it % STAGES;
        const uint32_t sA = smb + (uint32_t)st * STAGE_BYTES;
        const uint32_t sB = sA + BM * ROWB;

        #pragma unroll
        for (int kk = 0; kk < 4; kk++) {
            uint32_t a[4][4], b[4][2];
            #pragma unroll
            for (int mi = 0; mi < 4; mi++) {
                uint32_t addr = sA + (ar + (uint32_t)(mi * 16)) * ROWB + aoff[kk];
                asm volatile(
                    "ldmatrix.sync.aligned.m8n8.x4.shared.b16 {%0,%1,%2,%3}, [%4];"
                    : "=r"(a[mi][0]), "=r"(a[mi][1]), "=r"(a[mi][2]), "=r"(a[mi][3])
                    : "r"(addr));
            }
            #pragma unroll
            for (int nj = 0; nj < 4; nj++) {
                uint32_t addr = sB + (br + (uint32_t)(nj * 8)) * ROWB + boff[kk];
                asm volatile(
                    "ldmatrix.sync.aligned.m8n8.x2.shared.b16 {%0,%1}, [%2];"
                    : "=r"(b[nj][0]), "=r"(b[nj][1])
                    : "r"(addr));
            }
            #pragma unroll
            for (int mi = 0; mi < 4; mi++)
                #pragma unroll
                for (int nj = 0; nj < 4; nj++) {
                    float* cc = acc[mi][nj];
                    asm volatile(
                        "mma.sync.aligned.m16n8k8.row.col.f32.tf32.tf32.f32 "
                        "{%0,%1,%2,%3}, {%4,%5,%6,%7}, {%8,%9}, {%0,%1,%2,%3};\n"
                        : "+f"(cc[0]), "+f"(cc[1]), "+f"(cc[2]), "+f"(cc[3])
                        : "r"(a[mi][0]), "r"(a[mi][1]), "r"(a[mi][2]), "r"(a[mi][3]),
                          "r"(b[nj][0]), "r"(b[nj][1]));
                }
        }
    }

    // ---- epilogue: gate-scaled atomic accumulate into out ----
    #pragma unroll
    for (int mi = 0; mi < 4; mi++) {
        #pragma unroll
        for (int half = 0; half < 2; half++) {
            const int r = wm * 64 + mi * 16 + g4 + half * 8;
            const int p = row0 + r;
            if (p < end) {
                const float g = s_gate[r];
                float* orow = out + (size_t)s_tok[r] * D_OUT + n0;
                #pragma unroll
                for (int nj = 0; nj < 4; nj++) {
                    const int col = wn * 32 + nj * 8 + 2 * tg;
                    atomicAdd(&orow[col    ], g * acc[mi][nj][half * 2 + 0]);
                    atomicAdd(&orow[col + 1], g * acc[mi][nj][half * 2 + 1]);
                }
            }
        }
    }
}

// ---------------- launch ----------------
extern "C" void kernel_launch(void* const* d_in, const int* in_sizes, int n_in,
                              void* d_out, int out_size)
{
    const float* X = (const float*)d_in[0];
    const float* W = (const float*)d_in[1];
    const int *scat, *offs; const float* gates;
    if (n_in >= 8) {
        scat = (const int*)d_in[4]; offs = (const int*)d_in[6]; gates = (const float*)d_in[7];
    } else {
        scat = (const int*)d_in[3]; offs = (const int*)d_in[5]; gates = (const float*)d_in[6];
    }
    float* out = (float*)d_out;

    prep<<<NK, 256>>>(X, scat);
    cudaMemsetAsync(out, 0, (size_t)N_TOK * D_OUT * sizeof(float));

    const int dyn_smem = STAGES * STAGE_BYTES;   // 98304 B
    static bool attr_set = false;
    if (!attr_set) {
        cudaFuncSetAttribute(moe_mma, cudaFuncAttributeMaxDynamicSharedMemorySize, dyn_smem);
        attr_set = true;
    }

    dim3 grid(D_OUT / BN, N_EXP * MT);   // 16 x 256
    moe_mma<<<grid, 256, dyn_smem>>>(W, scat, offs, gates, out);
}